// round 6
// baseline (speedup 1.0000x reference)
#include <cuda_runtime.h>
#include <cuda_bf16.h>
#include <cstdint>

// ---------------- problem constants ----------------
#define T_TOK  32768
#define K_CODE 8192
#define D_DIM  128
#define NTILE  64            // K_CODE / 128 column tiles
#define DECAY  0.1f
#define OMD    0.9f
#define EPSF   1e-5f

// output layout (all fp32, concatenated in reference return order)
static const size_t OFF_I    = (size_t)T_TOK * D_DIM;             // after quantized
static const size_t OFF_DIST = OFF_I + T_TOK;                     // after indices
static const size_t OFF_NE   = OFF_DIST + (size_t)T_TOK * K_CODE; // after dist
static const size_t OFF_NCS  = OFF_NE + (size_t)K_CODE * D_DIM;   // after new_embed
static const size_t OFF_NEA  = OFF_NCS + K_CODE;                  // after new_cluster_size

// ---------------- device scratch (no allocations allowed) ----------------
__device__ __align__(16) __nv_bfloat16 g_Abf[(size_t)T_TOK * D_DIM];   // 8 MB
__device__ __align__(16) __nv_bfloat16 g_Bbf[(size_t)K_CODE * D_DIM];  // 2 MB
__device__ float g_x2[T_TOK];
__device__ float g_e2[K_CODE];
__device__ unsigned long long g_tbest[(size_t)T_TOK * NTILE];          // 16 MB
__device__ float g_cs[K_CODE];
__device__ __align__(16) float g_es[(size_t)K_CODE * D_DIM];           // 4 MB
__device__ float g_S;

__device__ __forceinline__ uint32_t smem_u32(const void* p) {
    return (uint32_t)__cvta_generic_to_shared(p);
}

// ---------------- kernels ----------------
__global__ void init_kernel() {
    size_t i = (size_t)blockIdx.x * 256 + threadIdx.x;   // grid 8192 -> 2,097,152 threads
    g_tbest[i] = ~0ull;
    if (i < (size_t)K_CODE * D_DIM) g_es[i] = 0.f;
    if (i < K_CODE) g_cs[i] = 0.f;
}

__global__ void prep_x_kernel(const float* __restrict__ x) {
    int t = blockIdx.x, d = threadIdx.x;
    float v = x[(size_t)t * D_DIM + d];
    g_Abf[(size_t)t * D_DIM + d] = __float2bfloat16(v);
    float s = v * v;
    for (int o = 16; o; o >>= 1) s += __shfl_xor_sync(0xffffffffu, s, o);
    __shared__ float ws[4];
    if ((d & 31) == 0) ws[d >> 5] = s;
    __syncthreads();
    if (d == 0) g_x2[t] = ws[0] + ws[1] + ws[2] + ws[3];
}

__global__ void prep_e_kernel(const float* __restrict__ embed) {
    int k = blockIdx.x, d = threadIdx.x;
    float v = embed[(size_t)k * D_DIM + d];
    g_Bbf[(size_t)k * D_DIM + d] = __float2bfloat16(v);
    float s = v * v;
    for (int o = 16; o; o >>= 1) s += __shfl_xor_sync(0xffffffffu, s, o);
    __shared__ float ws[4];
    if ((d & 31) == 0) ws[d >> 5] = s;
    __syncthreads();
    if (d == 0) g_e2[k] = ws[0] + ws[1] + ws[2] + ws[3];
}

// ---- GEMM: 128x128 CTA tile, K=128 in two 64-slabs, mma.sync bf16 ----
__global__ void __launch_bounds__(256, 2) gemm_kernel(float* __restrict__ dist) {
    __shared__ __align__(16) __nv_bfloat16 sA[128 * 64];   // 16 KB, xor-swizzled
    __shared__ __align__(16) __nv_bfloat16 sB[128 * 64];   // 16 KB
    const int tid = threadIdx.x, lane = tid & 31, wid = tid >> 5;
    const int bn = blockIdx.x & 63, bm = blockIdx.x >> 6;
    const int m0 = bm * 128, n0 = bn * 128;
    const int wm = wid >> 2, wn = wid & 3;     // warps 2 (M) x 4 (N), warp tile 64x32

    float acc[4][4][4];
#pragma unroll
    for (int a = 0; a < 4; ++a)
#pragma unroll
        for (int b = 0; b < 4; ++b)
#pragma unroll
            for (int c = 0; c < 4; ++c) acc[a][b][c] = 0.f;

    const uint32_t sA_u = smem_u32(sA), sB_u = smem_u32(sB);

#pragma unroll 1
    for (int slab = 0; slab < 2; ++slab) {
        // fill A/B slabs: 128 rows x 128B each = 1024 16B segments per matrix
#pragma unroll
        for (int it = 0; it < 4; ++it) {
            int s = tid + it * 256;
            int row = s >> 3, ch = s & 7;
            uint32_t so = (uint32_t)(row * 128 + ((ch ^ (row & 7)) << 4));
            const __nv_bfloat16* ga = g_Abf + (size_t)(m0 + row) * D_DIM + slab * 64 + ch * 8;
            asm volatile("cp.async.cg.shared.global [%0], [%1], 16;" :: "r"(sA_u + so), "l"(ga));
            const __nv_bfloat16* gb = g_Bbf + (size_t)(n0 + row) * D_DIM + slab * 64 + ch * 8;
            asm volatile("cp.async.cg.shared.global [%0], [%1], 16;" :: "r"(sB_u + so), "l"(gb));
        }
        asm volatile("cp.async.commit_group;");
        asm volatile("cp.async.wait_group 0;");
        __syncthreads();

#pragma unroll
        for (int kt = 0; kt < 4; ++kt) {
            uint32_t af[4][4];
            uint32_t bfr[4][2];
#pragma unroll
            for (int mt = 0; mt < 4; ++mt) {
                int r = wm * 64 + mt * 16 + (lane & 15);
                int ch = kt * 2 + (lane >> 4);
                uint32_t ad = sA_u + (uint32_t)(r * 128 + ((ch ^ (r & 7)) << 4));
                asm volatile("ldmatrix.sync.aligned.m8n8.x4.shared.b16 {%0,%1,%2,%3}, [%4];"
                    : "=r"(af[mt][0]), "=r"(af[mt][1]), "=r"(af[mt][2]), "=r"(af[mt][3])
                    : "r"(ad));
            }
#pragma unroll
            for (int p = 0; p < 2; ++p) {
                // B tile is n-major (row=code, col=k) == exactly the col-major k x n
                // operand layout -> NON-trans ldmatrix with n-row addresses.
                // lanes 0-7:  n rows 0-7,  k 0-7   -> reg0 = b0 of n-tile (p*2)
                // lanes 8-15: n rows 0-7,  k 8-15  -> reg1 = b1 of n-tile (p*2)
                // lanes 16-23:n rows 8-15, k 0-7   -> reg2 = b0 of n-tile (p*2+1)
                // lanes 24-31:n rows 8-15, k 8-15  -> reg3 = b1 of n-tile (p*2+1)
                int r = wn * 32 + p * 16 + ((lane >> 4) << 3) + (lane & 7);
                int ch = kt * 2 + ((lane >> 3) & 1);
                uint32_t bd = sB_u + (uint32_t)(r * 128 + ((ch ^ (r & 7)) << 4));
                asm volatile("ldmatrix.sync.aligned.m8n8.x4.shared.b16 {%0,%1,%2,%3}, [%4];"
                    : "=r"(bfr[p * 2][0]), "=r"(bfr[p * 2][1]),
                      "=r"(bfr[p * 2 + 1][0]), "=r"(bfr[p * 2 + 1][1])
                    : "r"(bd));
            }
#pragma unroll
            for (int mt = 0; mt < 4; ++mt)
#pragma unroll
                for (int nt = 0; nt < 4; ++nt)
                    asm volatile(
                        "mma.sync.aligned.m16n8k16.row.col.f32.bf16.bf16.f32 "
                        "{%0,%1,%2,%3}, {%4,%5,%6,%7}, {%8,%9}, {%0,%1,%2,%3};"
                        : "+f"(acc[mt][nt][0]), "+f"(acc[mt][nt][1]),
                          "+f"(acc[mt][nt][2]), "+f"(acc[mt][nt][3])
                        : "r"(af[mt][0]), "r"(af[mt][1]), "r"(af[mt][2]), "r"(af[mt][3]),
                          "r"(bfr[nt][0]), "r"(bfr[nt][1]));
        }
        __syncthreads();
    }

    // epilogue: dist = x2 + e2 - 2*dot; write + per-(row, CTA-n-tile) packed min
    const int g = lane >> 2, qd = lane & 3;
    float e2v[4][2];
#pragma unroll
    for (int nt = 0; nt < 4; ++nt) {
        int col = n0 + wn * 32 + nt * 8 + qd * 2;
        e2v[nt][0] = g_e2[col];
        e2v[nt][1] = g_e2[col + 1];
    }
#pragma unroll
    for (int mt = 0; mt < 4; ++mt) {
#pragma unroll
        for (int h = 0; h < 2; ++h) {
            int row = m0 + wm * 64 + mt * 16 + h * 8 + g;
            float x2v = g_x2[row];
            unsigned long long pk = ~0ull;
            float* dr = dist + (size_t)row * K_CODE + n0 + wn * 32;
#pragma unroll
            for (int nt = 0; nt < 4; ++nt) {
                float va = fmaf(-2.f, acc[mt][nt][h * 2 + 0], x2v + e2v[nt][0]);
                float vb = fmaf(-2.f, acc[mt][nt][h * 2 + 1], x2v + e2v[nt][1]);
                int col = n0 + wn * 32 + nt * 8 + qd * 2;
                *(float2*)(dr + nt * 8 + qd * 2) = make_float2(va, vb);
                unsigned long long pa =
                    ((unsigned long long)__float_as_uint(va) << 32) | (unsigned)col;
                unsigned long long pb =
                    ((unsigned long long)__float_as_uint(vb) << 32) | (unsigned)(col + 1);
                pk = pa < pk ? pa : pk;
                pk = pb < pk ? pb : pk;
            }
            unsigned long long t1 = __shfl_xor_sync(0xffffffffu, pk, 1);
            pk = t1 < pk ? t1 : pk;
            unsigned long long t2 = __shfl_xor_sync(0xffffffffu, pk, 2);
            pk = t2 < pk ? t2 : pk;
            if (qd == 0) atomicMin(&g_tbest[(size_t)row * NTILE + bn], pk);
        }
    }
}

// ---- pass2: exact fp32 argmin fixup + quantized/indices/EMA scatter ----
__global__ void __launch_bounds__(256) pass2_kernel(
    const float* __restrict__ x, const float* __restrict__ embed,
    const float* __restrict__ dist, float* __restrict__ out_q, float* __restrict__ out_i) {
    const int lane = threadIdx.x & 31;
    const int row = blockIdx.x * 8 + (threadIdx.x >> 5);

    const unsigned long long* tb = g_tbest + (size_t)row * NTILE;
    unsigned long long e0 = tb[lane], e1 = tb[lane + 32];
    unsigned long long mn = e0 < e1 ? e0 : e1;
#pragma unroll
    for (int o = 16; o; o >>= 1) {
        unsigned long long t = __shfl_xor_sync(0xffffffffu, mn, o);
        mn = t < mn ? t : mn;
    }
    const float thr = __uint_as_float((unsigned)(mn >> 32)) + 2.0f;  // b* + 2*margin

    const float4 xl4 = *(const float4*)(x + (size_t)row * D_DIM + lane * 4);
    float bestv = 3.402823466e+38f;
    int bestc = 0x7fffffff;

#pragma unroll 1
    for (int t = 0; t < NTILE; ++t) {
        unsigned long long tv = __shfl_sync(0xffffffffu, (t < 32) ? e0 : e1, t & 31);
        if (__uint_as_float((unsigned)(tv >> 32)) >= thr) continue;
        float4 dv = *(const float4*)(dist + (size_t)row * K_CODE + t * 128 + lane * 4);
        float dvv[4] = {dv.x, dv.y, dv.z, dv.w};
#pragma unroll
        for (int j = 0; j < 4; ++j) {
            unsigned mask = __ballot_sync(0xffffffffu, dvv[j] < thr);
            while (mask) {
                int l = __ffs(mask) - 1;
                mask &= mask - 1;
                int col = t * 128 + l * 4 + j;
                float4 ev = *(const float4*)(embed + (size_t)col * D_DIM + lane * 4);
                float d0 = xl4.x - ev.x, d1 = xl4.y - ev.y;
                float d2 = xl4.z - ev.z, d3 = xl4.w - ev.w;
                float s = d0 * d0 + d1 * d1 + d2 * d2 + d3 * d3;
#pragma unroll
                for (int o = 16; o; o >>= 1) s += __shfl_xor_sync(0xffffffffu, s, o);
                if (s < bestv || (s == bestv && col < bestc)) { bestv = s; bestc = col; }
            }
        }
    }

    if (lane == 0) {
        out_i[row] = (float)bestc;
        atomicAdd(&g_cs[bestc], 1.0f);
    }
    float4 ev = *(const float4*)(embed + (size_t)bestc * D_DIM + lane * 4);
    *(float4*)(out_q + (size_t)row * D_DIM + lane * 4) = ev;
    float* esr = g_es + (size_t)bestc * D_DIM + lane * 4;
    atomicAdd(esr + 0, xl4.x);
    atomicAdd(esr + 1, xl4.y);
    atomicAdd(esr + 2, xl4.z);
    atomicAdd(esr + 3, xl4.w);
}

__global__ void finalA_kernel(const float* __restrict__ clus, float* __restrict__ out_ncs) {
    int tid = threadIdx.x, lane = tid & 31, wid = tid >> 5;
    float s = 0.f;
    for (int k = tid; k < K_CODE; k += 1024) {
        float v = DECAY * clus[k] + OMD * g_cs[k];
        out_ncs[k] = v;
        s += v;
    }
    for (int o = 16; o; o >>= 1) s += __shfl_xor_sync(0xffffffffu, s, o);
    __shared__ float sred[32];
    if (lane == 0) sred[wid] = s;
    __syncthreads();
    if (wid == 0) {
        float v = sred[lane];
        for (int o = 16; o; o >>= 1) v += __shfl_xor_sync(0xffffffffu, v, o);
        if (lane == 0) g_S = v;
    }
}

__global__ void finalB_kernel(const float* __restrict__ eavg, const float* __restrict__ clus,
                              float* __restrict__ out_nea, float* __restrict__ out_ne) {
    int i = blockIdx.x * blockDim.x + threadIdx.x;   // 0 .. K*D-1
    int k = i >> 7;
    float nea = DECAY * eavg[i] + OMD * g_es[i];
    out_nea[i] = nea;
    float ncs = DECAY * clus[k] + OMD * g_cs[k];
    float norm = (ncs + EPSF) / (g_S + (float)K_CODE * EPSF);
    out_ne[i] = nea / norm;
}

// ---------------- launch ----------------
extern "C" void kernel_launch(void* const* d_in, const int* in_sizes, int n_in,
                              void* d_out, int out_size) {
    (void)in_sizes; (void)n_in; (void)out_size;
    const float* x     = (const float*)d_in[0];
    const float* embed = (const float*)d_in[1];
    const float* clus  = (const float*)d_in[2];
    const float* eavg  = (const float*)d_in[3];
    float* out = (float*)d_out;

    float* out_q    = out;
    float* out_i    = out + OFF_I;
    float* out_dist = out + OFF_DIST;
    float* out_ne   = out + OFF_NE;
    float* out_ncs  = out + OFF_NCS;
    float* out_nea  = out + OFF_NEA;

    init_kernel<<<(T_TOK * NTILE) / 256, 256>>>();
    prep_x_kernel<<<T_TOK, 128>>>(x);
    prep_e_kernel<<<K_CODE, 128>>>(embed);
    gemm_kernel<<<(T_TOK / 128) * (K_CODE / 128), 256>>>(out_dist);
    pass2_kernel<<<T_TOK / 8, 256>>>(x, embed, out_dist, out_q, out_i);
    finalA_kernel<<<1, 1024>>>(clus, out_ncs);
    finalB_kernel<<<(K_CODE * D_DIM) / 256, 256>>>(eavg, clus, out_nea, out_ne);
}

// round 7
// speedup vs baseline: 1.1304x; 1.1304x over previous
#include <cuda_runtime.h>
#include <cuda_bf16.h>
#include <cstdint>

// ---------------- problem constants ----------------
#define T_TOK  32768
#define K_CODE 8192
#define D_DIM  128
#define NTILE  64            // K_CODE / 128 column tiles
#define DECAY  0.1f
#define OMD    0.9f
#define EPSF   1e-5f

// output layout (all fp32, concatenated in reference return order)
static const size_t OFF_I    = (size_t)T_TOK * D_DIM;             // after quantized
static const size_t OFF_DIST = OFF_I + T_TOK;                     // after indices
static const size_t OFF_NE   = OFF_DIST + (size_t)T_TOK * K_CODE; // after dist
static const size_t OFF_NCS  = OFF_NE + (size_t)K_CODE * D_DIM;   // after new_embed
static const size_t OFF_NEA  = OFF_NCS + K_CODE;                  // after new_cluster_size

// ---------------- device scratch (no allocations allowed) ----------------
__device__ __align__(16) __nv_bfloat16 g_Abf[(size_t)T_TOK * D_DIM];   // 8 MB
__device__ __align__(16) __nv_bfloat16 g_Bbf[(size_t)K_CODE * D_DIM];  // 2 MB
__device__ float g_x2[T_TOK];
__device__ float g_e2[K_CODE];
__device__ unsigned long long g_tbest[(size_t)T_TOK * NTILE];          // 16 MB (no init needed)
__device__ float g_cs[K_CODE];
__device__ __align__(16) float g_es[(size_t)K_CODE * D_DIM];           // 4 MB
__device__ float g_S;

__device__ __forceinline__ uint32_t smem_u32(const void* p) {
    return (uint32_t)__cvta_generic_to_shared(p);
}

// ---------------- kernels ----------------
__global__ void init_kernel() {
    int i = blockIdx.x * 256 + threadIdx.x;              // grid 4096 -> 1,048,576 threads
    g_es[i] = 0.f;
    if (i < K_CODE) g_cs[i] = 0.f;
}

__global__ void prep_x_kernel(const float* __restrict__ x) {
    int t = blockIdx.x, d = threadIdx.x;
    float v = x[(size_t)t * D_DIM + d];
    g_Abf[(size_t)t * D_DIM + d] = __float2bfloat16(v);
    float s = v * v;
    for (int o = 16; o; o >>= 1) s += __shfl_xor_sync(0xffffffffu, s, o);
    __shared__ float ws[4];
    if ((d & 31) == 0) ws[d >> 5] = s;
    __syncthreads();
    if (d == 0) g_x2[t] = ws[0] + ws[1] + ws[2] + ws[3];
}

__global__ void prep_e_kernel(const float* __restrict__ embed) {
    int k = blockIdx.x, d = threadIdx.x;
    float v = embed[(size_t)k * D_DIM + d];
    g_Bbf[(size_t)k * D_DIM + d] = __float2bfloat16(v);
    float s = v * v;
    for (int o = 16; o; o >>= 1) s += __shfl_xor_sync(0xffffffffu, s, o);
    __shared__ float ws[4];
    if ((d & 31) == 0) ws[d >> 5] = s;
    __syncthreads();
    if (d == 0) g_e2[k] = ws[0] + ws[1] + ws[2] + ws[3];
}

// ---- GEMM: 128x128 CTA tile, K=128 in two 64-slabs, both prefetched ----
// dynamic smem: A0 @0, B0 @16K, A1 @32K, B1 @48K  (64 KB total)
#define SLAB_BYTES 16384
#define GEMM_SMEM  65536

__device__ __forceinline__ void fill_slab(uint32_t sA_u, uint32_t sB_u,
                                          int m0, int n0, int slab, int tid) {
#pragma unroll
    for (int it = 0; it < 4; ++it) {
        int s = tid + it * 256;
        int row = s >> 3, ch = s & 7;
        uint32_t so = (uint32_t)(row * 128 + ((ch ^ (row & 7)) << 4));
        const __nv_bfloat16* ga = g_Abf + (size_t)(m0 + row) * D_DIM + slab * 64 + ch * 8;
        asm volatile("cp.async.cg.shared.global [%0], [%1], 16;" :: "r"(sA_u + so), "l"(ga));
        const __nv_bfloat16* gb = g_Bbf + (size_t)(n0 + row) * D_DIM + slab * 64 + ch * 8;
        asm volatile("cp.async.cg.shared.global [%0], [%1], 16;" :: "r"(sB_u + so), "l"(gb));
    }
    asm volatile("cp.async.commit_group;");
}

__global__ void __launch_bounds__(256, 2) gemm_kernel(float* __restrict__ dist) {
    extern __shared__ char dsm[];
    const uint32_t s_u = smem_u32(dsm);
    const int tid = threadIdx.x, lane = tid & 31, wid = tid >> 5;
    const int bn = blockIdx.x & 63, bm = blockIdx.x >> 6;
    const int m0 = bm * 128, n0 = bn * 128;
    const int wm = wid >> 2, wn = wid & 3;     // warps 2 (M) x 4 (N), warp tile 64x32

    // prefetch BOTH K-slabs (two commit groups)
    fill_slab(s_u, s_u + SLAB_BYTES, m0, n0, 0, tid);
    fill_slab(s_u + 2 * SLAB_BYTES, s_u + 3 * SLAB_BYTES, m0, n0, 1, tid);

    float acc[4][4][4];
#pragma unroll
    for (int a = 0; a < 4; ++a)
#pragma unroll
        for (int b = 0; b < 4; ++b)
#pragma unroll
            for (int c = 0; c < 4; ++c) acc[a][b][c] = 0.f;

#pragma unroll 1
    for (int slab = 0; slab < 2; ++slab) {
        if (slab == 0) asm volatile("cp.async.wait_group 1;");
        else           asm volatile("cp.async.wait_group 0;");
        __syncthreads();
        const uint32_t sA_u = s_u + slab * 2 * SLAB_BYTES;
        const uint32_t sB_u = sA_u + SLAB_BYTES;

#pragma unroll
        for (int kt = 0; kt < 4; ++kt) {
            uint32_t af[4][4];
            uint32_t bfr[4][2];
#pragma unroll
            for (int mt = 0; mt < 4; ++mt) {
                int r = wm * 64 + mt * 16 + (lane & 15);
                int ch = kt * 2 + (lane >> 4);
                uint32_t ad = sA_u + (uint32_t)(r * 128 + ((ch ^ (r & 7)) << 4));
                asm volatile("ldmatrix.sync.aligned.m8n8.x4.shared.b16 {%0,%1,%2,%3}, [%4];"
                    : "=r"(af[mt][0]), "=r"(af[mt][1]), "=r"(af[mt][2]), "=r"(af[mt][3])
                    : "r"(ad));
            }
#pragma unroll
            for (int p = 0; p < 2; ++p) {
                // B tile is n-major == col-major k x n operand -> NON-trans ldmatrix
                int r = wn * 32 + p * 16 + ((lane >> 4) << 3) + (lane & 7);
                int ch = kt * 2 + ((lane >> 3) & 1);
                uint32_t bd = sB_u + (uint32_t)(r * 128 + ((ch ^ (r & 7)) << 4));
                asm volatile("ldmatrix.sync.aligned.m8n8.x4.shared.b16 {%0,%1,%2,%3}, [%4];"
                    : "=r"(bfr[p * 2][0]), "=r"(bfr[p * 2][1]),
                      "=r"(bfr[p * 2 + 1][0]), "=r"(bfr[p * 2 + 1][1])
                    : "r"(bd));
            }
#pragma unroll
            for (int mt = 0; mt < 4; ++mt)
#pragma unroll
                for (int nt = 0; nt < 4; ++nt)
                    asm volatile(
                        "mma.sync.aligned.m16n8k16.row.col.f32.bf16.bf16.f32 "
                        "{%0,%1,%2,%3}, {%4,%5,%6,%7}, {%8,%9}, {%0,%1,%2,%3};"
                        : "+f"(acc[mt][nt][0]), "+f"(acc[mt][nt][1]),
                          "+f"(acc[mt][nt][2]), "+f"(acc[mt][nt][3])
                        : "r"(af[mt][0]), "r"(af[mt][1]), "r"(af[mt][2]), "r"(af[mt][3]),
                          "r"(bfr[nt][0]), "r"(bfr[nt][1]));
        }
    }

    // epilogue: dist = x2 + e2 - 2*dot; write dist + per-row min via smem reduction
    // (slab-0 smem region is dead now; reuse it: u64[localrow * 4 + wn])
    unsigned long long* smin = (unsigned long long*)dsm;
    const int g = lane >> 2, qd = lane & 3;
    float e2v[4][2];
#pragma unroll
    for (int nt = 0; nt < 4; ++nt) {
        int col = n0 + wn * 32 + nt * 8 + qd * 2;
        e2v[nt][0] = g_e2[col];
        e2v[nt][1] = g_e2[col + 1];
    }
#pragma unroll
    for (int mt = 0; mt < 4; ++mt) {
#pragma unroll
        for (int h = 0; h < 2; ++h) {
            int lrow = wm * 64 + mt * 16 + h * 8 + g;
            int row = m0 + lrow;
            float x2v = g_x2[row];
            unsigned long long pk = ~0ull;
            float* dr = dist + (size_t)row * K_CODE + n0 + wn * 32;
#pragma unroll
            for (int nt = 0; nt < 4; ++nt) {
                float va = fmaf(-2.f, acc[mt][nt][h * 2 + 0], x2v + e2v[nt][0]);
                float vb = fmaf(-2.f, acc[mt][nt][h * 2 + 1], x2v + e2v[nt][1]);
                int col = n0 + wn * 32 + nt * 8 + qd * 2;
                *(float2*)(dr + nt * 8 + qd * 2) = make_float2(va, vb);
                unsigned long long pa =
                    ((unsigned long long)__float_as_uint(va) << 32) | (unsigned)col;
                unsigned long long pb =
                    ((unsigned long long)__float_as_uint(vb) << 32) | (unsigned)(col + 1);
                pk = pa < pk ? pa : pk;
                pk = pb < pk ? pb : pk;
            }
            unsigned long long t1 = __shfl_xor_sync(0xffffffffu, pk, 1);
            pk = t1 < pk ? t1 : pk;
            unsigned long long t2 = __shfl_xor_sync(0xffffffffu, pk, 2);
            pk = t2 < pk ? t2 : pk;
            if (qd == 0) smin[lrow * 4 + wn] = pk;
        }
    }
    __syncthreads();
    if (tid < 128) {
        unsigned long long m01 = smin[tid * 4 + 0] < smin[tid * 4 + 1]
                               ? smin[tid * 4 + 0] : smin[tid * 4 + 1];
        unsigned long long m23 = smin[tid * 4 + 2] < smin[tid * 4 + 3]
                               ? smin[tid * 4 + 2] : smin[tid * 4 + 3];
        g_tbest[(size_t)(m0 + tid) * NTILE + bn] = m01 < m23 ? m01 : m23;
    }
}

// ---- pass2: exact fp32 argmin fixup + quantized/indices/EMA scatter ----
__global__ void __launch_bounds__(256) pass2_kernel(
    const float* __restrict__ x, const float* __restrict__ embed,
    const float* __restrict__ dist, float* __restrict__ out_q, float* __restrict__ out_i) {
    const int lane = threadIdx.x & 31;
    const int row = blockIdx.x * 8 + (threadIdx.x >> 5);

    const unsigned long long* tb = g_tbest + (size_t)row * NTILE;
    unsigned long long e0 = tb[lane], e1 = tb[lane + 32];
    unsigned long long mn = e0 < e1 ? e0 : e1;
#pragma unroll
    for (int o = 16; o; o >>= 1) {
        unsigned long long t = __shfl_xor_sync(0xffffffffu, mn, o);
        mn = t < mn ? t : mn;
    }
    const float thr = __uint_as_float((unsigned)(mn >> 32)) + 2.0f;  // b* + 2*margin

    const float4 xl4 = *(const float4*)(x + (size_t)row * D_DIM + lane * 4);
    float bestv = 3.402823466e+38f;
    int bestc = 0x7fffffff;

#pragma unroll 1
    for (int t = 0; t < NTILE; ++t) {
        unsigned long long tv = __shfl_sync(0xffffffffu, (t < 32) ? e0 : e1, t & 31);
        if (__uint_as_float((unsigned)(tv >> 32)) >= thr) continue;
        float4 dv = *(const float4*)(dist + (size_t)row * K_CODE + t * 128 + lane * 4);
        float dvv[4] = {dv.x, dv.y, dv.z, dv.w};
#pragma unroll
        for (int j = 0; j < 4; ++j) {
            unsigned mask = __ballot_sync(0xffffffffu, dvv[j] < thr);
            while (mask) {
                int l = __ffs(mask) - 1;
                mask &= mask - 1;
                int col = t * 128 + l * 4 + j;
                float4 ev = *(const float4*)(embed + (size_t)col * D_DIM + lane * 4);
                float d0 = xl4.x - ev.x, d1 = xl4.y - ev.y;
                float d2 = xl4.z - ev.z, d3 = xl4.w - ev.w;
                float s = d0 * d0 + d1 * d1 + d2 * d2 + d3 * d3;
#pragma unroll
                for (int o = 16; o; o >>= 1) s += __shfl_xor_sync(0xffffffffu, s, o);
                if (s < bestv || (s == bestv && col < bestc)) { bestv = s; bestc = col; }
            }
        }
    }

    if (lane == 0) {
        out_i[row] = (float)bestc;
        atomicAdd(&g_cs[bestc], 1.0f);
    }
    float4 ev = *(const float4*)(embed + (size_t)bestc * D_DIM + lane * 4);
    *(float4*)(out_q + (size_t)row * D_DIM + lane * 4) = ev;
    float* esr = g_es + (size_t)bestc * D_DIM + lane * 4;
    atomicAdd(esr + 0, xl4.x);
    atomicAdd(esr + 1, xl4.y);
    atomicAdd(esr + 2, xl4.z);
    atomicAdd(esr + 3, xl4.w);
}

__global__ void finalA_kernel(const float* __restrict__ clus, float* __restrict__ out_ncs) {
    int tid = threadIdx.x, lane = tid & 31, wid = tid >> 5;
    float s = 0.f;
    for (int k = tid; k < K_CODE; k += 1024) {
        float v = DECAY * clus[k] + OMD * g_cs[k];
        out_ncs[k] = v;
        s += v;
    }
    for (int o = 16; o; o >>= 1) s += __shfl_xor_sync(0xffffffffu, s, o);
    __shared__ float sred[32];
    if (lane == 0) sred[wid] = s;
    __syncthreads();
    if (wid == 0) {
        float v = sred[lane];
        for (int o = 16; o; o >>= 1) v += __shfl_xor_sync(0xffffffffu, v, o);
        if (lane == 0) g_S = v;
    }
}

__global__ void finalB_kernel(const float* __restrict__ eavg, const float* __restrict__ clus,
                              float* __restrict__ out_nea, float* __restrict__ out_ne) {
    int i = blockIdx.x * blockDim.x + threadIdx.x;   // 0 .. K*D-1
    int k = i >> 7;
    float nea = DECAY * eavg[i] + OMD * g_es[i];
    out_nea[i] = nea;
    float ncs = DECAY * clus[k] + OMD * g_cs[k];
    float norm = (ncs + EPSF) / (g_S + (float)K_CODE * EPSF);
    out_ne[i] = nea / norm;
}

// ---------------- launch ----------------
extern "C" void kernel_launch(void* const* d_in, const int* in_sizes, int n_in,
                              void* d_out, int out_size) {
    (void)in_sizes; (void)n_in; (void)out_size;
    const float* x     = (const float*)d_in[0];
    const float* embed = (const float*)d_in[1];
    const float* clus  = (const float*)d_in[2];
    const float* eavg  = (const float*)d_in[3];
    float* out = (float*)d_out;

    float* out_q    = out;
    float* out_i    = out + OFF_I;
    float* out_dist = out + OFF_DIST;
    float* out_ne   = out + OFF_NE;
    float* out_ncs  = out + OFF_NCS;
    float* out_nea  = out + OFF_NEA;

    static bool attr_set = false;
    if (!attr_set) {
        cudaFuncSetAttribute(gemm_kernel, cudaFuncAttributeMaxDynamicSharedMemorySize,
                             GEMM_SMEM);
        attr_set = true;
    }

    init_kernel<<<(K_CODE * D_DIM) / 256, 256>>>();
    prep_x_kernel<<<T_TOK, 128>>>(x);
    prep_e_kernel<<<K_CODE, 128>>>(embed);
    gemm_kernel<<<(T_TOK / 128) * (K_CODE / 128), 256, GEMM_SMEM>>>(out_dist);
    pass2_kernel<<<T_TOK / 8, 256>>>(x, embed, out_dist, out_q, out_i);
    finalA_kernel<<<1, 1024>>>(clus, out_ncs);
    finalB_kernel<<<(K_CODE * D_DIM) / 256, 256>>>(eavg, clus, out_nea, out_ne);
}

// round 8
// speedup vs baseline: 1.2447x; 1.1011x over previous
#include <cuda_runtime.h>
#include <cuda_bf16.h>
#include <cstdint>

// ---------------- problem constants ----------------
#define T_TOK  32768
#define K_CODE 8192
#define D_DIM  128
#define NTILE  64            // K_CODE / 128 column tiles
#define DECAY  0.1f
#define OMD    0.9f
#define EPSF   1e-5f

// output layout (all fp32, concatenated in reference return order)
static const size_t OFF_I    = (size_t)T_TOK * D_DIM;             // after quantized
static const size_t OFF_DIST = OFF_I + T_TOK;                     // after indices
static const size_t OFF_NE   = OFF_DIST + (size_t)T_TOK * K_CODE; // after dist
static const size_t OFF_NCS  = OFF_NE + (size_t)K_CODE * D_DIM;   // after new_embed
static const size_t OFF_NEA  = OFF_NCS + K_CODE;                  // after new_cluster_size

// ---------------- device scratch (no allocations allowed) ----------------
__device__ __align__(16) __nv_bfloat16 g_Abf[(size_t)T_TOK * D_DIM];   // 8 MB
__device__ __align__(16) __nv_bfloat16 g_Bbf[(size_t)K_CODE * D_DIM];  // 2 MB
__device__ float g_x2[T_TOK];
__device__ float g_e2[K_CODE];
__device__ unsigned long long g_tbest[(size_t)T_TOK * NTILE];          // 16 MB (fully overwritten)
__device__ float g_cs[K_CODE];
__device__ __align__(16) float g_es[(size_t)K_CODE * D_DIM];           // 4 MB
__device__ float g_S;

__device__ __forceinline__ uint32_t smem_u32(const void* p) {
    return (uint32_t)__cvta_generic_to_shared(p);
}

// ---------------- prep kernels (warp-per-row, float4) ----------------
__global__ void __launch_bounds__(256) prep_x_kernel(const float* __restrict__ x) {
    int t = blockIdx.x * 8 + (threadIdx.x >> 5);     // token
    int lane = threadIdx.x & 31;
    float4 v = *(const float4*)(x + (size_t)t * D_DIM + lane * 4);
    __nv_bfloat162 p0, p1;
    p0.x = __float2bfloat16(v.x); p0.y = __float2bfloat16(v.y);
    p1.x = __float2bfloat16(v.z); p1.y = __float2bfloat16(v.w);
    __nv_bfloat162* dst = (__nv_bfloat162*)(g_Abf + (size_t)t * D_DIM + lane * 4);
    dst[0] = p0; dst[1] = p1;
    float s = v.x * v.x + v.y * v.y + v.z * v.z + v.w * v.w;
    for (int o = 16; o; o >>= 1) s += __shfl_xor_sync(0xffffffffu, s, o);
    if (lane == 0) g_x2[t] = s;
}

__global__ void __launch_bounds__(256) prep_e_kernel(const float* __restrict__ embed) {
    int k = blockIdx.x * 8 + (threadIdx.x >> 5);     // code
    int lane = threadIdx.x & 31;
    float4 v = *(const float4*)(embed + (size_t)k * D_DIM + lane * 4);
    __nv_bfloat162 p0, p1;
    p0.x = __float2bfloat16(v.x); p0.y = __float2bfloat16(v.y);
    p1.x = __float2bfloat16(v.z); p1.y = __float2bfloat16(v.w);
    __nv_bfloat162* dst = (__nv_bfloat162*)(g_Bbf + (size_t)k * D_DIM + lane * 4);
    dst[0] = p0; dst[1] = p1;
    // zero EMA scratch (replaces init_kernel)
    *(float4*)(g_es + (size_t)k * D_DIM + lane * 4) = make_float4(0.f, 0.f, 0.f, 0.f);
    float s = v.x * v.x + v.y * v.y + v.z * v.z + v.w * v.w;
    for (int o = 16; o; o >>= 1) s += __shfl_xor_sync(0xffffffffu, s, o);
    if (lane == 0) { g_e2[k] = s; g_cs[k] = 0.f; }
}

// ---- GEMM: 128x128 CTA tile, K=128 in two 64-slabs, both prefetched ----
// dynamic smem: A0 @0, B0 @16K, A1 @32K, B1 @48K  (64 KB total)
// B columns are PERMUTED within each 32-row span at fill time:
//   smem row s holds global code pi(s),  pi(s) = 16*(s>>4) + 4*((s&7)>>1) + 2*((s>>3)&1) + (s&1)
// so that accumulator fragment (nt, 2*qd+j) maps to global col
//   16*(nt>>1) + 4*qd + 2*(nt&1) + j  -> each thread owns 8 CONSECUTIVE cols.
#define SLAB_BYTES 16384
#define GEMM_SMEM  65536

__device__ __forceinline__ void fill_slab(uint32_t sA_u, uint32_t sB_u,
                                          int m0, int n0, int slab, int tid) {
#pragma unroll
    for (int it = 0; it < 4; ++it) {
        int s = tid + it * 256;
        int row = s >> 3, ch = s & 7;
        uint32_t so = (uint32_t)(row * 128 + ((ch ^ (row & 7)) << 4));
        const __nv_bfloat16* ga = g_Abf + (size_t)(m0 + row) * D_DIM + slab * 64 + ch * 8;
        asm volatile("cp.async.cg.shared.global [%0], [%1], 16;" :: "r"(sA_u + so), "l"(ga));
        int s5 = row & 31;
        int prow = (row & 96) + ((s5 & 16) | (((s5 >> 1) & 3) << 2) | (((s5 >> 3) & 1) << 1) | (s5 & 1));
        const __nv_bfloat16* gb = g_Bbf + (size_t)(n0 + prow) * D_DIM + slab * 64 + ch * 8;
        asm volatile("cp.async.cg.shared.global [%0], [%1], 16;" :: "r"(sB_u + so), "l"(gb));
    }
    asm volatile("cp.async.commit_group;");
}

__global__ void __launch_bounds__(256, 2) gemm_kernel(float* __restrict__ dist) {
    extern __shared__ char dsm[];
    const uint32_t s_u = smem_u32(dsm);
    const int tid = threadIdx.x, lane = tid & 31, wid = tid >> 5;
    const int bn = blockIdx.x & 63, bm = blockIdx.x >> 6;
    const int m0 = bm * 128, n0 = bn * 128;
    const int wm = wid >> 2, wn = wid & 3;     // warps 2 (M) x 4 (N), warp tile 64x32

    // prefetch BOTH K-slabs (two commit groups)
    fill_slab(s_u, s_u + SLAB_BYTES, m0, n0, 0, tid);
    fill_slab(s_u + 2 * SLAB_BYTES, s_u + 3 * SLAB_BYTES, m0, n0, 1, tid);

    float acc[4][4][4];
#pragma unroll
    for (int a = 0; a < 4; ++a)
#pragma unroll
        for (int b = 0; b < 4; ++b)
#pragma unroll
            for (int c = 0; c < 4; ++c) acc[a][b][c] = 0.f;

#pragma unroll 1
    for (int slab = 0; slab < 2; ++slab) {
        if (slab == 0) asm volatile("cp.async.wait_group 1;");
        else           asm volatile("cp.async.wait_group 0;");
        __syncthreads();
        const uint32_t sA_u = s_u + slab * 2 * SLAB_BYTES;
        const uint32_t sB_u = sA_u + SLAB_BYTES;

#pragma unroll
        for (int kt = 0; kt < 4; ++kt) {
            uint32_t af[4][4];
            uint32_t bfr[4][2];
#pragma unroll
            for (int mt = 0; mt < 4; ++mt) {
                int r = wm * 64 + mt * 16 + (lane & 15);
                int ch = kt * 2 + (lane >> 4);
                uint32_t ad = sA_u + (uint32_t)(r * 128 + ((ch ^ (r & 7)) << 4));
                asm volatile("ldmatrix.sync.aligned.m8n8.x4.shared.b16 {%0,%1,%2,%3}, [%4];"
                    : "=r"(af[mt][0]), "=r"(af[mt][1]), "=r"(af[mt][2]), "=r"(af[mt][3])
                    : "r"(ad));
            }
#pragma unroll
            for (int p = 0; p < 2; ++p) {
                // identity ldmatrix addressing; column permutation lives in smem content
                int r = wn * 32 + p * 16 + ((lane >> 4) << 3) + (lane & 7);
                int ch = kt * 2 + ((lane >> 3) & 1);
                uint32_t bd = sB_u + (uint32_t)(r * 128 + ((ch ^ (r & 7)) << 4));
                asm volatile("ldmatrix.sync.aligned.m8n8.x4.shared.b16 {%0,%1,%2,%3}, [%4];"
                    : "=r"(bfr[p * 2][0]), "=r"(bfr[p * 2][1]),
                      "=r"(bfr[p * 2 + 1][0]), "=r"(bfr[p * 2 + 1][1])
                    : "r"(bd));
            }
#pragma unroll
            for (int mt = 0; mt < 4; ++mt)
#pragma unroll
                for (int nt = 0; nt < 4; ++nt)
                    asm volatile(
                        "mma.sync.aligned.m16n8k16.row.col.f32.bf16.bf16.f32 "
                        "{%0,%1,%2,%3}, {%4,%5,%6,%7}, {%8,%9}, {%0,%1,%2,%3};"
                        : "+f"(acc[mt][nt][0]), "+f"(acc[mt][nt][1]),
                          "+f"(acc[mt][nt][2]), "+f"(acc[mt][nt][3])
                        : "r"(af[mt][0]), "r"(af[mt][1]), "r"(af[mt][2]), "r"(af[mt][3]),
                          "r"(bfr[nt][0]), "r"(bfr[nt][1]));
        }
    }

    // epilogue: dist = x2 + e2 - 2*dot; each thread owns 8 consecutive cols
    // at cb = n0 + wn*32 + 4*qd (cols cb..cb+3) and cb+16 (cols cb+16..cb+19)
    unsigned long long* smin = (unsigned long long*)dsm;   // reuse slab0 region
    const int g = lane >> 2, qd = lane & 3;
    const int cb = n0 + wn * 32 + 4 * qd;
    const float4 e2a = *(const float4*)(g_e2 + cb);
    const float4 e2b = *(const float4*)(g_e2 + cb + 16);
#pragma unroll
    for (int mt = 0; mt < 4; ++mt) {
#pragma unroll
        for (int h = 0; h < 2; ++h) {
            int lrow = wm * 64 + mt * 16 + h * 8 + g;
            int row = m0 + lrow;
            float x2v = g_x2[row];
            // float4 #0: nt0,nt1 -> cols cb..cb+3 ; float4 #1: nt2,nt3 -> cols cb+16..cb+19
            float4 va, vb;
            va.x = fmaf(-2.f, acc[mt][0][h * 2 + 0], x2v + e2a.x);
            va.y = fmaf(-2.f, acc[mt][0][h * 2 + 1], x2v + e2a.y);
            va.z = fmaf(-2.f, acc[mt][1][h * 2 + 0], x2v + e2a.z);
            va.w = fmaf(-2.f, acc[mt][1][h * 2 + 1], x2v + e2a.w);
            vb.x = fmaf(-2.f, acc[mt][2][h * 2 + 0], x2v + e2b.x);
            vb.y = fmaf(-2.f, acc[mt][2][h * 2 + 1], x2v + e2b.y);
            vb.z = fmaf(-2.f, acc[mt][3][h * 2 + 0], x2v + e2b.z);
            vb.w = fmaf(-2.f, acc[mt][3][h * 2 + 1], x2v + e2b.w);
            float* dr = dist + (size_t)row * K_CODE + cb;
            *(float4*)dr = va;
            *(float4*)(dr + 16) = vb;
            unsigned long long pk = ~0ull;
            {
                const float vv[8] = {va.x, va.y, va.z, va.w, vb.x, vb.y, vb.z, vb.w};
#pragma unroll
                for (int j = 0; j < 8; ++j) {
                    int col = cb + (j < 4 ? j : 12 + j);   // +16 offset for second group
                    unsigned long long pj =
                        ((unsigned long long)__float_as_uint(vv[j]) << 32) | (unsigned)col;
                    pk = pj < pk ? pj : pk;
                }
            }
            unsigned long long t1 = __shfl_xor_sync(0xffffffffu, pk, 1);
            pk = t1 < pk ? t1 : pk;
            unsigned long long t2 = __shfl_xor_sync(0xffffffffu, pk, 2);
            pk = t2 < pk ? t2 : pk;
            if (qd == 0) smin[lrow * 4 + wn] = pk;
        }
    }
    __syncthreads();
    if (tid < 128) {
        unsigned long long m01 = smin[tid * 4 + 0] < smin[tid * 4 + 1]
                               ? smin[tid * 4 + 0] : smin[tid * 4 + 1];
        unsigned long long m23 = smin[tid * 4 + 2] < smin[tid * 4 + 3]
                               ? smin[tid * 4 + 2] : smin[tid * 4 + 3];
        g_tbest[(size_t)(m0 + tid) * NTILE + bn] = m01 < m23 ? m01 : m23;
    }
}

// ---- pass2: exact fp32 argmin fixup + quantized/indices/EMA scatter ----
__global__ void __launch_bounds__(256) pass2_kernel(
    const float* __restrict__ x, const float* __restrict__ embed,
    const float* __restrict__ dist, float* __restrict__ out_q, float* __restrict__ out_i) {
    const int lane = threadIdx.x & 31;
    const int row = blockIdx.x * 8 + (threadIdx.x >> 5);

    const unsigned long long* tb = g_tbest + (size_t)row * NTILE;
    unsigned long long e0 = tb[lane], e1 = tb[lane + 32];
    unsigned long long mn = e0 < e1 ? e0 : e1;
#pragma unroll
    for (int o = 16; o; o >>= 1) {
        unsigned long long t = __shfl_xor_sync(0xffffffffu, mn, o);
        mn = t < mn ? t : mn;
    }
    const float thr = __uint_as_float((unsigned)(mn >> 32)) + 2.0f;  // b* + 2*margin

    const float4 xl4 = *(const float4*)(x + (size_t)row * D_DIM + lane * 4);
    float bestv = 3.402823466e+38f;
    int bestc = 0x7fffffff;

#pragma unroll 1
    for (int t = 0; t < NTILE; ++t) {
        unsigned long long tv = __shfl_sync(0xffffffffu, (t < 32) ? e0 : e1, t & 31);
        if (__uint_as_float((unsigned)(tv >> 32)) >= thr) continue;
        float4 dv = *(const float4*)(dist + (size_t)row * K_CODE + t * 128 + lane * 4);
        float dvv[4] = {dv.x, dv.y, dv.z, dv.w};
#pragma unroll
        for (int j = 0; j < 4; ++j) {
            unsigned mask = __ballot_sync(0xffffffffu, dvv[j] < thr);
            while (mask) {
                int l = __ffs(mask) - 1;
                mask &= mask - 1;
                int col = t * 128 + l * 4 + j;
                float4 ev = *(const float4*)(embed + (size_t)col * D_DIM + lane * 4);
                float d0 = xl4.x - ev.x, d1 = xl4.y - ev.y;
                float d2 = xl4.z - ev.z, d3 = xl4.w - ev.w;
                float s = d0 * d0 + d1 * d1 + d2 * d2 + d3 * d3;
#pragma unroll
                for (int o = 16; o; o >>= 1) s += __shfl_xor_sync(0xffffffffu, s, o);
                if (s < bestv || (s == bestv && col < bestc)) { bestv = s; bestc = col; }
            }
        }
    }

    if (lane == 0) {
        out_i[row] = (float)bestc;
        atomicAdd(&g_cs[bestc], 1.0f);
    }
    float4 ev = *(const float4*)(embed + (size_t)bestc * D_DIM + lane * 4);
    *(float4*)(out_q + (size_t)row * D_DIM + lane * 4) = ev;
    float* esr = g_es + (size_t)bestc * D_DIM + lane * 4;
    atomicAdd(esr + 0, xl4.x);
    atomicAdd(esr + 1, xl4.y);
    atomicAdd(esr + 2, xl4.z);
    atomicAdd(esr + 3, xl4.w);
}

__global__ void finalA_kernel(const float* __restrict__ clus, float* __restrict__ out_ncs) {
    int tid = threadIdx.x, lane = tid & 31, wid = tid >> 5;
    float s = 0.f;
    for (int k = tid; k < K_CODE; k += 1024) {
        float v = DECAY * clus[k] + OMD * g_cs[k];
        out_ncs[k] = v;
        s += v;
    }
    for (int o = 16; o; o >>= 1) s += __shfl_xor_sync(0xffffffffu, s, o);
    __shared__ float sred[32];
    if (lane == 0) sred[wid] = s;
    __syncthreads();
    if (wid == 0) {
        float v = sred[lane];
        for (int o = 16; o; o >>= 1) v += __shfl_xor_sync(0xffffffffu, v, o);
        if (lane == 0) g_S = v;
    }
}

__global__ void finalB_kernel(const float* __restrict__ eavg, const float* __restrict__ clus,
                              float* __restrict__ out_nea, float* __restrict__ out_ne) {
    int i = blockIdx.x * blockDim.x + threadIdx.x;   // 0 .. K*D-1
    int k = i >> 7;
    float nea = DECAY * eavg[i] + OMD * g_es[i];
    out_nea[i] = nea;
    float ncs = DECAY * clus[k] + OMD * g_cs[k];
    float norm = (ncs + EPSF) / (g_S + (float)K_CODE * EPSF);
    out_ne[i] = nea / norm;
}

// ---------------- launch ----------------
extern "C" void kernel_launch(void* const* d_in, const int* in_sizes, int n_in,
                              void* d_out, int out_size) {
    (void)in_sizes; (void)n_in; (void)out_size;
    const float* x     = (const float*)d_in[0];
    const float* embed = (const float*)d_in[1];
    const float* clus  = (const float*)d_in[2];
    const float* eavg  = (const float*)d_in[3];
    float* out = (float*)d_out;

    float* out_q    = out;
    float* out_i    = out + OFF_I;
    float* out_dist = out + OFF_DIST;
    float* out_ne   = out + OFF_NE;
    float* out_ncs  = out + OFF_NCS;
    float* out_nea  = out + OFF_NEA;

    static bool attr_set = false;
    if (!attr_set) {
        cudaFuncSetAttribute(gemm_kernel, cudaFuncAttributeMaxDynamicSharedMemorySize,
                             GEMM_SMEM);
        attr_set = true;
    }

    prep_x_kernel<<<T_TOK / 8, 256>>>(x);
    prep_e_kernel<<<K_CODE / 8, 256>>>(embed);
    gemm_kernel<<<(T_TOK / 128) * (K_CODE / 128), 256, GEMM_SMEM>>>(out_dist);
    pass2_kernel<<<T_TOK / 8, 256>>>(x, embed, out_dist, out_q, out_i);
    finalA_kernel<<<1, 1024>>>(clus, out_ncs);
    finalB_kernel<<<(K_CODE * D_DIM) / 256, 256>>>(eavg, clus, out_nea, out_ne);
}